// round 16
// baseline (speedup 1.0000x reference)
#include <cuda_runtime.h>
#include <cuda_fp16.h>
#include <cstdint>
#include <cstddef>

// ===================== problem constants =====================
constexpr int C    = 128;            // channels
constexpr int NET  = 7;              // edge types
constexpr int NMAX = 100000;
constexpr int NPAD = 100096;         // 782 * 128 (GEMM grid coverage)
constexpr int KTOT = NET * C;        // 896
constexpr int NCH  = 14;             // K chunks of 64 halfs (32 uints)
constexpr int NSEGMAX = NMAX * NET;  // 700000
constexpr int EMAX = 700000;
constexpr int SCAN_BLK = 1024;

// ===================== device scratch ========================
__device__ unsigned g_cnt[NSEGMAX];             // zero-init; re-zeroed by scan
__device__ unsigned g_off[NSEGMAX + 1];         // CSR offsets
__device__ unsigned g_cur[NSEGMAX];             // fill cursors
__device__ int      g_elist[EMAX];              // col index per CSR slot
__device__ unsigned g_ticket;                   // zero-init; re-zeroed by fill
__device__ unsigned long long g_state[1024];    // zero-init; re-zeroed by fill
__device__ float    g_stats[2 * C];             // zeroed by count each replay
__device__ uint32_t g_wh[KTOT * C / 2];         // W fp16 pairs [k][n/2]  (448 KB)
__device__ uint32_t g_ah[(size_t)NCH * NPAD * 32];  // A fp16 CHUNK-MAJOR [chunk][row][32u]

// ===================== helpers ===============================
__device__ __forceinline__ uint32_t pack_h2(float a, float b) {
    __half2 h = __floats2half2_rn(a, b);
    return *reinterpret_cast<uint32_t*>(&h);
}
__device__ __forceinline__ uint32_t smem_u32(const void* p) {
    uint32_t a;
    asm("{ .reg .u64 t; cvta.to.shared.u64 t, %1; cvt.u32.u64 %0, t; }" : "=r"(a) : "l"(p));
    return a;
}
__device__ __forceinline__ void mma_f16(float* d, const uint32_t* a, uint32_t b0, uint32_t b1) {
    asm volatile(
        "mma.sync.aligned.m16n8k16.row.col.f32.f16.f16.f32 "
        "{%0,%1,%2,%3}, {%4,%5,%6,%7}, {%8,%9}, {%0,%1,%2,%3};"
        : "+f"(d[0]), "+f"(d[1]), "+f"(d[2]), "+f"(d[3])
        : "r"(a[0]), "r"(a[1]), "r"(a[2]), "r"(a[3]), "r"(b0), "r"(b1));
}
#define LDSM_X4(r, addr)                                                        \
    asm volatile("ldmatrix.sync.aligned.m8n8.x4.shared.b16 {%0,%1,%2,%3}, [%4];"\
        : "=r"((r)[0]), "=r"((r)[1]), "=r"((r)[2]), "=r"((r)[3]) : "r"(addr))
#define LDSM_X4_T(r, addr)                                                      \
    asm volatile("ldmatrix.sync.aligned.m8n8.x4.trans.shared.b16 {%0,%1,%2,%3}, [%4];"\
        : "=r"((r)[0]), "=r"((r)[1]), "=r"((r)[2]), "=r"((r)[3]) : "r"(addr))
__device__ __forceinline__ void cp_async16(uint32_t dst, const void* src) {
    asm volatile("cp.async.cg.shared.global [%0], [%1], 16;" :: "r"(dst), "l"(src));
}
#define CP_COMMIT() asm volatile("cp.async.commit_group;" ::: "memory")
#define CP_WAIT(n)  asm volatile("cp.async.wait_group %0;" :: "n"(n) : "memory")

__device__ unsigned block_incl_scan(unsigned v, unsigned* wsum) {
    int lane = threadIdx.x & 31, wid = threadIdx.x >> 5;
#pragma unroll
    for (int d = 1; d < 32; d <<= 1) {
        unsigned n = __shfl_up_sync(0xffffffff, v, d);
        if (lane >= d) v += n;
    }
    if (lane == 31) wsum[wid] = v;
    __syncthreads();
    if (wid == 0) {
        unsigned w = wsum[lane];
#pragma unroll
        for (int d = 1; d < 32; d <<= 1) {
            unsigned n = __shfl_up_sync(0xffffffff, w, d);
            if (lane >= d) w += n;
        }
        wsum[lane] = w;
    }
    __syncthreads();
    return v + (wid > 0 ? wsum[wid - 1] : 0u);
}

// ===================== CSR build =============================
// packs W to fp16, zeroes BN stats, counts segments
__global__ void count_kernel(const int* __restrict__ row,
                             const int* __restrict__ et,
                             const float* __restrict__ w, int E) {
    int e = blockIdx.x * blockDim.x + threadIdx.x;
    if (e < KTOT * C / 2) {
        float2 v = reinterpret_cast<const float2*>(w)[e];
        g_wh[e] = pack_h2(v.x, v.y);
    }
    if (e < 2 * C) g_stats[e] = 0.f;
    if (e >= E) return;
    int t = et[e];
    if (t == NET - 1) return;
    atomicAdd(&g_cnt[row[e] * NET + t], 1u);
}

// single-pass decoupled-lookback exclusive scan; also re-zeroes g_cnt
__global__ void __launch_bounds__(SCAN_BLK) scan_kernel(int nseg) {
    __shared__ unsigned wsum[32];
    __shared__ unsigned s_bid, s_total, s_prefix;
    int tid = threadIdx.x;
    if (tid == 0) s_bid = atomicAdd(&g_ticket, 1u);
    __syncthreads();
    unsigned bid = s_bid;
    int i = bid * SCAN_BLK + tid;
    unsigned v = (i < nseg) ? g_cnt[i] : 0u;
    if (i < nseg) g_cnt[i] = 0u;                 // restore for next replay
    unsigned incl = block_incl_scan(v, wsum);
    if (tid == SCAN_BLK - 1) s_total = incl;
    __syncthreads();
    if (tid == 0) {
        unsigned total = s_total;
        if (bid == 0) {
            atomicExch(&g_state[0], (2ULL << 32) | (unsigned long long)total);
            s_prefix = 0u;
        } else {
            atomicExch(&g_state[bid], (1ULL << 32) | (unsigned long long)total);
            unsigned running = 0u;
            int idx = (int)bid - 1;
            while (true) {
                unsigned long long s;
                do { s = atomicAdd(&g_state[idx], 0ULL); } while ((unsigned)(s >> 32) == 0u);
                running += (unsigned)s;
                if ((unsigned)(s >> 32) == 2u) break;
                --idx;
            }
            s_prefix = running;
            atomicExch(&g_state[bid], (2ULL << 32) | (unsigned long long)(running + total));
        }
    }
    __syncthreads();
    unsigned off = s_prefix + incl - v;
    if (i < nseg) {
        g_off[i] = off;
        g_cur[i] = off;
        if (i == nseg - 1) g_off[nseg] = off + v;
    }
}

// fill CSR edge list; also re-zeroes scan state for next replay
__global__ void fill_kernel(const int* __restrict__ row,
                            const int* __restrict__ col,
                            const int* __restrict__ et, int E) {
    int e = blockIdx.x * blockDim.x + threadIdx.x;
    if (e < 1024) g_state[e] = 0ULL;
    if (e == 0) g_ticket = 0u;
    if (e >= E) return;
    int t = et[e];
    if (t == NET - 1) return;
    int seg = row[e] * NET + t;
    unsigned pos = atomicAdd(&g_cur[seg], 1u);
    g_elist[pos] = col[e];
}

// ===================== gather: warp-per-node, no barriers ====
// Writes A chunk-major: slot t -> chunks 2t, 2t+1. lanes 0-15 chunk lo, 16-31 hi.
__global__ void __launch_bounds__(256) gather_kernel(const float* __restrict__ x, int nrows) {
    int wrp = (blockIdx.x * 256 + threadIdx.x) >> 5;
    int lane = threadIdx.x & 31;
    if (wrp >= nrows) return;
    const float4* x4 = reinterpret_cast<const float4*>(x);
    const size_t dbase = ((size_t)(lane >> 4) * NPAD + wrp) * 32 + (lane & 15) * 2;
    // self slot (t = 6) -> chunks 12, 13
    float4 v = x4[(size_t)wrp * 32 + lane];
    *reinterpret_cast<uint2*>(g_ah + dbase + (size_t)12 * NPAD * 32) =
        make_uint2(pack_h2(v.x, v.y), pack_h2(v.z, v.w));
    int base = wrp * NET;
#pragma unroll
    for (int t = 0; t < NET - 1; ++t) {
        unsigned beg = g_off[base + t], end = g_off[base + t + 1];
        float4 a = make_float4(0.f, 0.f, 0.f, 0.f);
        for (unsigned e = beg; e < end; ++e) {
            int c = g_elist[e];
            float4 xv = x4[(size_t)c * 32 + lane];
            a.x += xv.x; a.y += xv.y; a.z += xv.z; a.w += xv.w;
        }
        if (end > beg) {
            float inv = 1.0f / (float)(end - beg);
            a.x *= inv; a.y *= inv; a.z *= inv; a.w *= inv;
        }
        *reinterpret_cast<uint2*>(g_ah + dbase + (size_t)(2 * t) * NPAD * 32) =
            make_uint2(pack_h2(a.x, a.y), pack_h2(a.z, a.w));
    }
}

// ===================== pipelined GEMM + BN stats =============
// CTA 128x128, 512 threads, 14 chunks, 3-stage cp.async, 1 barrier/chunk.
// A reads are CONTIGUOUS 16 KB per CTA-chunk (chunk-major g_ah).
constexpr int AP2 = 36;          // uints per A smem row (144 B)
constexpr int BP2 = 68;          // uints per B smem k-row (272 B)
constexpr int ASTAGE = 128 * AP2 * 4;      // 18432 B
constexpr int BSTAGE = 64 * BP2 * 4;       // 17408 B
constexpr int STAGE  = ASTAGE + BSTAGE;    // 35840 B
constexpr int OFF_STAT_B = 3 * STAGE;      // 107520
constexpr size_t GEMM_SMEM = OFF_STAT_B + 2 * C * 4;  // 108544 B (2 CTAs/SM)

#define GEMM_LOAD(cc, ss) do {                                                  \
    uint32_t _ab = sbase + (ss) * STAGE;                                        \
    const uint32_t* _as = aS + (size_t)(cc) * (NPAD * 32);                      \
    cp_async16(_ab + adst, _as);                                                \
    cp_async16(_ab + adst + 64 * (AP2 * 4), _as + 64 * 32);                     \
    const uint32_t* _bs = bS + (cc) * 4096;                                     \
    cp_async16(_ab + bdst, _bs);                                                \
    cp_async16(_ab + bdst + 32 * (BP2 * 4), _bs + 32 * 64);                     \
    CP_COMMIT();                                                                \
} while (0)

__global__ void __launch_bounds__(512, 2)
gemm_kernel(float* __restrict__ out, int nrows) {
    extern __shared__ uint32_t smu[];
    float* sstat = reinterpret_cast<float*>(smu + OFF_STAT_B / 4);

    const int tid = threadIdx.x;
    const int wid = tid >> 5, lane = tid & 31;
    const int m0 = blockIdx.x * 128;
    if (tid < 2 * C) sstat[tid] = 0.f;

    const uint32_t sbase = smem_u32(smu);
    const int wm = (wid >> 2) * 32, wn = (wid & 3) * 32;
    const int gr = lane >> 2, gc = lane & 3;
    const int grp = lane >> 3, rr = lane & 7;

    const uint32_t aoff0 = (wm + (grp & 1) * 8 + rr) * (AP2 * 4) + (grp >> 1) * 16;
    const uint32_t aoff1 = aoff0 + 16 * (AP2 * 4);
    const uint32_t boff0 = ASTAGE + ((grp & 1) * 8 + rr) * (BP2 * 4) + (wn + (grp >> 1) * 8) * 2;
    const uint32_t boff1 = boff0 + 32;

    // A: 8 thr/row of 128B; rows ar, ar+64. Contiguous global source per chunk.
    const int ar = tid >> 3, apos = tid & 7;
    const int bk = tid >> 4, bpos = tid & 15;
    const uint32_t adst = ar * (AP2 * 4) + apos * 16;
    const uint32_t bdst = ASTAGE + bk * (BP2 * 4) + bpos * 16;
    const uint32_t* aS = g_ah + (size_t)(m0 + ar) * 32 + apos * 4;
    const uint32_t* bS = g_wh + (size_t)bk * 64 + bpos * 4;

    float acc[2][4][4];
#pragma unroll
    for (int f = 0; f < 2; ++f)
#pragma unroll
        for (int g = 0; g < 4; ++g)
#pragma unroll
            for (int q = 0; q < 4; ++q) acc[f][g][q] = 0.f;

    GEMM_LOAD(0, 0);
    GEMM_LOAD(1, 1);
    int cur = 0;

    for (int c = 0; c < NCH; ++c) {
        if (c < NCH - 1) { CP_WAIT(1); } else { CP_WAIT(0); }
        __syncthreads();                     // single barrier per chunk
        if (c + 2 < NCH) {
            int nxt = (cur == 0) ? 2 : cur - 1;   // (cur+2)%3
            GEMM_LOAD(c + 2, nxt);
        }
        uint32_t abuf = sbase + cur * STAGE;
#pragma unroll
        for (int ks = 0; ks < 4; ++ks) {
            uint32_t af0[4], af1[4], bf0[4], bf1[4];
            LDSM_X4(af0, abuf + aoff0 + ks * 32);
            LDSM_X4(af1, abuf + aoff1 + ks * 32);
            LDSM_X4_T(bf0, abuf + boff0 + ks * 16 * (BP2 * 4));
            LDSM_X4_T(bf1, abuf + boff1 + ks * 16 * (BP2 * 4));
            mma_f16(acc[0][0], af0, bf0[0], bf0[1]);
            mma_f16(acc[0][1], af0, bf0[2], bf0[3]);
            mma_f16(acc[0][2], af0, bf1[0], bf1[1]);
            mma_f16(acc[0][3], af0, bf1[2], bf1[3]);
            mma_f16(acc[1][0], af1, bf0[0], bf0[1]);
            mma_f16(acc[1][1], af1, bf0[2], bf0[3]);
            mma_f16(acc[1][2], af1, bf1[0], bf1[1]);
            mma_f16(acc[1][3], af1, bf1[2], bf1[3]);
        }
        cur = (cur == 2) ? 0 : cur + 1;
    }

    // ---- epilogue: write out once + fused BN stats ----
#pragma unroll
    for (int f = 0; f < 2; ++f) {
        int r0 = m0 + wm + 16 * f + gr;
#pragma unroll
        for (int g = 0; g < 4; ++g) {
            int cn = wn + 8 * g + gc * 2;
            float s0 = 0.f, q0 = 0.f, s1 = 0.f, q1 = 0.f;
            if (r0 < nrows) {
                float v0 = acc[f][g][0], v1 = acc[f][g][1];
                *reinterpret_cast<float2*>(&out[(size_t)r0 * C + cn]) = make_float2(v0, v1);
                s0 += v0; q0 += v0 * v0; s1 += v1; q1 += v1 * v1;
            }
            if (r0 + 8 < nrows) {
                float v0 = acc[f][g][2], v1 = acc[f][g][3];
                *reinterpret_cast<float2*>(&out[(size_t)(r0 + 8) * C + cn]) = make_float2(v0, v1);
                s0 += v0; q0 += v0 * v0; s1 += v1; q1 += v1 * v1;
            }
            atomicAdd(&sstat[cn], s0);
            atomicAdd(&sstat[C + cn], q0);
            atomicAdd(&sstat[cn + 1], s1);
            atomicAdd(&sstat[C + cn + 1], q1);
        }
    }
    __syncthreads();
    if (tid < 2 * C) atomicAdd(&g_stats[tid], sstat[tid]);
}

// ===================== normalize (scale/shift per block) =====
__global__ void norm_kernel(float* __restrict__ out,
                            const float* __restrict__ gamma,
                            const float* __restrict__ beta,
                            float inv_n, size_t n4) {
    __shared__ float ssc[C], ssh[C];
    int tid = threadIdx.x;
    if (tid < C) {
        float mean = g_stats[tid] * inv_n;
        float var  = g_stats[C + tid] * inv_n - mean * mean;
        float sc   = gamma[tid] * rsqrtf(var + 1e-5f);
        ssc[tid] = sc;
        ssh[tid] = beta[tid] - mean * sc;
    }
    __syncthreads();
    size_t i = (size_t)blockIdx.x * blockDim.x + tid;
    size_t stride = (size_t)gridDim.x * blockDim.x;
    const float4* sc4 = reinterpret_cast<const float4*>(ssc);
    const float4* sh4 = reinterpret_cast<const float4*>(ssh);
    float4* o4 = reinterpret_cast<float4*>(out);
    for (size_t j = i; j < n4; j += stride) {
        int c4 = (int)(j & 31);
        float4 v = o4[j];
        float4 a = sc4[c4], b = sh4[c4];
        v.x = v.x * a.x + b.x;
        v.y = v.y * a.y + b.y;
        v.z = v.z * a.z + b.z;
        v.w = v.w * a.w + b.w;
        o4[j] = v;
    }
}

// ===================== launch ================================
extern "C" void kernel_launch(void* const* d_in, const int* in_sizes, int n_in,
                              void* d_out, int out_size) {
    const float* x     = (const float*)d_in[0];
    const int*   row   = (const int*)d_in[1];   // JAX x64-disabled: int32
    const int*   col   = (const int*)d_in[2];
    const int*   et    = (const int*)d_in[3];
    const float* w     = (const float*)d_in[4];
    const float* gamma = (const float*)d_in[5];
    const float* beta  = (const float*)d_in[6];
    float* out = (float*)d_out;

    int nrows = in_sizes[0] / C;          // 100000
    int E     = in_sizes[1];              // 700000
    int nseg  = nrows * NET;
    int nblk  = (nseg + SCAN_BLK - 1) / SCAN_BLK;

    cudaFuncSetAttribute(gemm_kernel, cudaFuncAttributeMaxDynamicSharedMemorySize,
                         (int)GEMM_SMEM);

    count_kernel<<<(E + 255) / 256, 256>>>(row, et, w, E);                      // 0
    scan_kernel<<<nblk, SCAN_BLK>>>(nseg);                                      // 1
    fill_kernel<<<(E + 255) / 256, 256>>>(row, col, et, E);                     // 2
    gather_kernel<<<(nrows * 32 + 255) / 256, 256>>>(x, nrows);                 // 3 <- profiled
    gemm_kernel<<<(nrows + 127) / 128, 512, GEMM_SMEM>>>(out, nrows);           // 4
    norm_kernel<<<2048, 256>>>(out, gamma, beta, 1.0f / (float)nrows,
                               (size_t)nrows * 32);                             // 5
}